// round 16
// baseline (speedup 1.0000x reference)
#include <cuda_runtime.h>
#include <cuda_bf16.h>
#include <cstdint>

#define DIMK   4096
#define NEXP   64
#define BTOK   16384
#define MTILE  128
#define KB     64
#define NCH    (DIMK / KB)
#define NTHR   512
#define ABUF   16384                // per A buffer: A0(8K)+A1(8K), rows 0-63 bf16
#define STG_OFF 32768               // stages: Hs(16K fp32) + Ws(16K fp32) + B0/B1(16K bf16)
#define STG    49152
#define NSTG   3
#define BIAS_OFF 180224
#define CNT_OFF  180480
#define LIST_OFF 180496             // 64 ints
#define P_OFF    180752             // [8][64] floats
#define LR_OFF   182800             // 64 floats
#define SMEM_BYTES 183072
#define DELTA  1e-3f

// pre-split, pre-swizzled w tiles for the MMA side: [chunk][split][64e*64k bf16]
static __device__ __align__(16) unsigned short g_ws[NCH][2][4096];

__device__ __forceinline__ unsigned smem_u32(const void* p) {
    return (unsigned)__cvta_generic_to_shared(p);
}
__device__ __forceinline__ void cpa16(unsigned dst, const void* src) {
    asm volatile("cp.async.cg.shared.global [%0], [%1], 16;" :: "r"(dst), "l"(src));
}
__device__ __forceinline__ unsigned packbf(float hi, float lo) {
    unsigned r;
    asm("cvt.rn.bf16x2.f32 %0, %1, %2;" : "=r"(r) : "f"(hi), "f"(lo));
    return r;
}
__device__ __forceinline__ unsigned prmt_hi(unsigned a, unsigned b) {
    unsigned r;
    asm("prmt.b32 %0, %1, %2, 0x7632;" : "=r"(r) : "r"(a), "r"(b));
    return r;
}
__device__ __forceinline__ void ldsm4(unsigned* r, unsigned a) {
    asm volatile("ldmatrix.sync.aligned.m8n8.x4.shared.b16 {%0,%1,%2,%3}, [%4];"
                 : "=r"(r[0]), "=r"(r[1]), "=r"(r[2]), "=r"(r[3]) : "r"(a));
}
__device__ __forceinline__ void ffma2(unsigned long long& d,
                                      unsigned long long a,
                                      unsigned long long b) {
    asm("fma.rn.f32x2 %0, %1, %2, %0;" : "+l"(d) : "l"(a), "l"(b));
}
#define MMA(d, a, b0v, b1v)                                                    \
    asm volatile(                                                              \
        "mma.sync.aligned.m16n8k16.row.col.f32.bf16.bf16.f32 "                 \
        "{%0,%1,%2,%3},{%4,%5,%6,%7},{%8,%9},{%0,%1,%2,%3};"                   \
        : "+f"((d)[0]), "+f"((d)[1]), "+f"((d)[2]), "+f"((d)[3])               \
        : "r"((a)[0]), "r"((a)[1]), "r"((a)[2]), "r"((a)[3]),                  \
          "r"(b0v), "r"(b1v))

__global__ void wsplit_kernel(const float* __restrict__ w) {
    const int idx = blockIdx.x * 256 + threadIdx.x;
    const int e = idx >> 12, k = idx & 4095;
    const float x = w[idx];
    const unsigned short b0 = __bfloat16_as_ushort(__float2bfloat16(x));
    const float r = x - __uint_as_float((unsigned)b0 << 16);
    const unsigned short b1 = __bfloat16_as_ushort(__float2bfloat16(r));
    const int c = k >> 6, kk = k & 63;
    const unsigned off = ((unsigned)e << 7) + (((unsigned)kk * 2) ^ ((e & 7) << 4));
    g_ws[c][0][off >> 1] = b0;
    g_ws[c][1][off >> 1] = b1;
}

__global__ void __launch_bounds__(NTHR, 1)
mome_gate_hyb(const float* __restrict__ h,
              const float* __restrict__ w,
              const float* __restrict__ bias,
              float* __restrict__ out)
{
    extern __shared__ char smc[];
    const unsigned smb = smem_u32(smc);
    const int tid  = threadIdx.x;
    const int lane = tid & 31;
    const int wid  = tid >> 5;       // 0..15 ; 0-7 MMA (rows 0-63), 8-15 FFMA2 (rows 64-127)
    const size_t rowBase = (size_t)blockIdx.x * MTILE;

    if (tid == 0) *(int*)(smc + CNT_OFF) = 0;
    if (tid < NEXP) ((float*)(smc + BIAS_OFF))[tid] = bias[tid];

    // ---------- MMA-warp geometry (R13-proven) ----------
    const int wr = wid >> 1;         // 0..3 -> rows wr*16..+15
    const int we = wid & 1;          // experts we*32..+31
    const int mrow  = (lane & 7) + ((lane >> 3) & 1) * 8;
    const unsigned klane = ((unsigned)(lane >> 4)) * 16;
    const unsigned xorv  = ((unsigned)(lane & 7)) << 4;
    const unsigned aoff    = (unsigned)(wr * 16 + mrow) * 128;
    const unsigned browoff = (unsigned)(we * 32 + mrow) * 128;

    // ---------- FFMA2-warp geometry (R15-style, strided = conflict-free) ----------
    const int fw = wid - 8;          // 0..7
    const int frBase = (fw >> 1) * 16 + (lane >> 3);  // + 4*i -> local rows 0..63
    const int feBase = (fw & 1) * 32 + (lane & 7);    // + 8*j -> experts 0..63

    float accM[4][4];
    unsigned long long accF[4][4];
#pragma unroll
    for (int i = 0; i < 4; i++)
#pragma unroll
        for (int j = 0; j < 4; j++) { accM[i][j] = 0.f; accF[i][j] = 0ull; }

    // ---------- producers (all 512 threads) ----------
    float4 rga[2];
    auto ldgA = [&](int c) {         // MMA rows 0-63, fp32 -> regs
#pragma unroll
        for (int j = 0; j < 2; j++) {
            const int idx = tid + j * 512;
            const int row = idx >> 4, u4 = idx & 15;
            rga[j] = *(const float4*)(h + (rowBase + row) * DIMK + c * KB + u4 * 4);
        }
    };
    auto stsA = [&](int buf) {       // convert to bf16 A0/A1 tiles
        char* A0 = smc + buf * ABUF;
        char* A1 = A0 + 8192;
#pragma unroll
        for (int j = 0; j < 2; j++) {
            const int idx = tid + j * 512;
            const int row = idx >> 4, u4 = idx & 15;
            const unsigned boff = (unsigned)row * 128
                                + (((unsigned)u4 * 8) ^ (((unsigned)row & 7) << 4));
            const float4 v = rga[j];
            const unsigned hx = __float_as_uint(v.x), hy = __float_as_uint(v.y);
            const unsigned hz = __float_as_uint(v.z), hw = __float_as_uint(v.w);
            *(uint2*)(A0 + boff) = make_uint2(prmt_hi(hx, hy), prmt_hi(hz, hw));
            const float rx = v.x - __uint_as_float(hx & 0xffff0000u);
            const float ry = v.y - __uint_as_float(hy & 0xffff0000u);
            const float rz = v.z - __uint_as_float(hz & 0xffff0000u);
            const float rw = v.w - __uint_as_float(hw & 0xffff0000u);
            *(uint2*)(A1 + boff) = make_uint2(packbf(ry, rx), packbf(rw, rz));
        }
    };
    auto cpStage = [&](int c, int s) {
        const unsigned sb = smb + STG_OFF + s * STG;
        // Hs: rows 64-127 fp32, XOR-swizzled (8B units)
#pragma unroll
        for (int j = 0; j < 2; j++) {
            const int idx = tid + j * 512;
            const int r2 = idx >> 4, u4 = idx & 15;
            const unsigned du = ((unsigned)(2 * u4)) ^ (((unsigned)(r2 & 7)) << 2);
            cpa16(sb + (unsigned)r2 * 256 + (du << 3),
                  h + (rowBase + 64 + r2) * DIMK + c * KB + u4 * 4);
        }
        // Ws: 64 experts fp32, XOR-swizzled
#pragma unroll
        for (int j = 0; j < 2; j++) {
            const int idx = tid + j * 512;
            const int e = idx >> 4, u4 = idx & 15;
            const unsigned du = ((unsigned)(2 * u4)) ^ (((unsigned)(e & 7)) << 2);
            cpa16(sb + 16384 + (unsigned)e * 256 + (du << 3),
                  w + (size_t)e * DIMK + c * KB + u4 * 4);
        }
        // B bf16 splits (pre-swizzled in gmem)
        cpa16(sb + 32768 + tid * 16, (const char*)g_ws[c][0] + tid * 16);
        cpa16(sb + 40960 + tid * 16, (const char*)g_ws[c][1] + tid * 16);
        asm volatile("cp.async.commit_group;" ::: "memory");
    };

    // ---------- consumers ----------
    auto computeM = [&](int c, int s) {
        const unsigned Ab0 = smb + (c & 1) * ABUF + aoff;
        const unsigned Ab1 = Ab0 + 8192;
        const unsigned Bb0 = smb + STG_OFF + s * STG + 32768 + browoff;
        const unsigned Bb1 = Bb0 + 8192;
#pragma unroll
        for (int kb = 0; kb < 4; kb++) {
            const unsigned ko = ((unsigned)kb * 32 + klane) ^ xorv;
            unsigned a0f[4], a1f[4], b00[4], b01[4], b10[4], b11[4];
            ldsm4(a0f, Ab0 + ko);
            ldsm4(a1f, Ab1 + ko);
            ldsm4(b00, Bb0 + ko);
            ldsm4(b01, Bb0 + 2048 + ko);
            ldsm4(b10, Bb1 + ko);
            ldsm4(b11, Bb1 + 2048 + ko);

            MMA(accM[0], a0f, b00[0], b00[2]);
            MMA(accM[1], a0f, b00[1], b00[3]);
            MMA(accM[2], a0f, b01[0], b01[2]);
            MMA(accM[3], a0f, b01[1], b01[3]);
            MMA(accM[0], a0f, b10[0], b10[2]);
            MMA(accM[1], a0f, b10[1], b10[3]);
            MMA(accM[2], a0f, b11[0], b11[2]);
            MMA(accM[3], a0f, b11[1], b11[3]);
            MMA(accM[0], a1f, b00[0], b00[2]);
            MMA(accM[1], a1f, b00[1], b00[3]);
            MMA(accM[2], a1f, b01[0], b01[2]);
            MMA(accM[3], a1f, b01[1], b01[3]);
        }
    };
    auto computeF = [&](int s) {
        const char* Hb = smc + STG_OFF + s * STG;
        const char* Wb = Hb + 16384;
#pragma unroll
        for (int k4 = 0; k4 < 16; k4++) {
            const unsigned p = (unsigned)(k4 * 2);
            ulonglong2 hv[4], wv[4];
#pragma unroll
            for (int i = 0; i < 4; i++) {
                const int r2 = frBase + 4 * i;
                const unsigned x = ((unsigned)(r2 & 7)) << 2;
                hv[i] = *(const ulonglong2*)(Hb + r2 * 256 + ((p ^ x) << 3));
            }
#pragma unroll
            for (int j = 0; j < 4; j++) {
                const int e = feBase + 8 * j;
                const unsigned x = ((unsigned)(e & 7)) << 2;
                wv[j] = *(const ulonglong2*)(Wb + e * 256 + ((p ^ x) << 3));
            }
#pragma unroll
            for (int i = 0; i < 4; i++)
#pragma unroll
                for (int j = 0; j < 4; j++) {
                    ffma2(accF[i][j], hv[i].x, wv[j].x);
                    ffma2(accF[i][j], hv[i].y, wv[j].y);
                }
        }
    };

    // ---------- pipeline (R12/R13-proven shape) ----------
    ldgA(0);
    stsA(0);
    ldgA(1);
    cpStage(0, 0);
    cpStage(1, 1);

    int s = 0;
    for (int c = 0; c < NCH; c++) {
        asm volatile("cp.async.wait_group 1;" ::: "memory");
        __syncthreads();
        if (c + 1 < NCH) stsA((c + 1) & 1);
        if (c + 2 < NCH) {
            ldgA(c + 2);
            int ns = s + 2; if (ns >= NSTG) ns -= NSTG;
            cpStage(c + 2, ns);
        }
        if (wid < 8) computeM(c, s);
        else         computeF(s);
        if (++s == NSTG) s = 0;
    }
    asm volatile("cp.async.wait_group 0;" ::: "memory");
    __syncthreads();

    // ---------- logits -> smem: Ls[128][68] ----------
    float* Ls = (float*)smc;
    if (wid < 8) {
        const int rin = lane >> 2;
        const int cin = (lane & 3) * 2;
        const int r0i = wr * 16 + rin;
#pragma unroll
        for (int n = 0; n < 4; n++) {
            const int col = we * 32 + n * 8 + cin;
            Ls[r0i * 68 + col]           = accM[n][0];
            Ls[r0i * 68 + col + 1]       = accM[n][1];
            Ls[(r0i + 8) * 68 + col]     = accM[n][2];
            Ls[(r0i + 8) * 68 + col + 1] = accM[n][3];
        }
    } else {
#pragma unroll
        for (int i = 0; i < 4; i++) {
            const int row = 64 + frBase + 4 * i;
#pragma unroll
            for (int j = 0; j < 4; j++) {
                const int e = feBase + 8 * j;
                const unsigned long long a = accF[i][j];
                const float lo = __uint_as_float((unsigned)(a & 0xffffffffull));
                const float hi = __uint_as_float((unsigned)(a >> 32));
                Ls[row * 68 + e] = lo + hi;
            }
        }
    }
    __syncthreads();

    // ---------- per-row top-3 scan, flag near-ties (R13-verbatim) ----------
    const float* bias_s = (const float*)(smc + BIAS_OFF);
    if (tid < MTILE) {
        const float* lrow = &Ls[tid * 68];
        float v0 = -1e30f, v1 = -1e30f, v2 = -1e30f;
        int i0 = 0, i1 = 0;
#pragma unroll 8
        for (int e = 0; e < NEXP; e++) {
            const float v = lrow[e] + bias_s[e];
            if (v > v0)      { v2 = v1; v1 = v0; i1 = i0; v0 = v; i0 = e; }
            else if (v > v1) { v2 = v1; v1 = v; i1 = e; }
            else if (v > v2) { v2 = v; }
        }
        if ((v0 - v1 < DELTA) || (v1 - v2 < DELTA)) {
            const int slot = atomicAdd((int*)(smc + CNT_OFF), 1);
            if (slot < 64) ((int*)(smc + LIST_OFF))[slot] = tid;
        } else {
            const float t  = __expf(v1 - v0);
            const float w0 = 1.0f / (1.0f + t);
            const size_t g = rowBase + tid;
            out[2 * g]     = w0;
            out[2 * g + 1] = 1.0f - w0;
            float* oi = out + 2 * (size_t)BTOK;
            oi[2 * g]     = (float)i0;
            oi[2 * g + 1] = (float)i1;
        }
    }
    __syncthreads();

    // ---------- exact fp32 rescue (R13-verbatim) ----------
    int nf = *(const int*)(smc + CNT_OFF);
    if (nf > 64) nf = 64;
    float* P  = (float*)(smc + P_OFF);     // [8][64]
    float* Lr = (float*)(smc + LR_OFF);    // [64]
    for (int f = 0; f < nf; f++) {
        const int rrow = ((const int*)(smc + LIST_OFF))[f];
        const float* hr = h + (rowBase + rrow) * DIMK;
        const int e = tid & 63, q = tid >> 6;   // q 0..7
        const float* wp = w + (size_t)e * DIMK + q * 512;
        const float* hp = hr + q * 512;
        float sacc = 0.f;
        for (int k = 0; k < 512; k += 4) {
            const float4 hv = *(const float4*)(hp + k);
            const float4 wv = *(const float4*)(wp + k);
            sacc += hv.x * wv.x + hv.y * wv.y + hv.z * wv.z + hv.w * wv.w;
        }
        P[q * 64 + e] = sacc;
        __syncthreads();
        if (tid < NEXP) {
            float acc2 = bias_s[tid];
#pragma unroll
            for (int q2 = 0; q2 < 8; q2++) acc2 += P[q2 * 64 + tid];
            Lr[tid] = acc2;
        }
        __syncthreads();
        if (tid == 0) {
            float v0 = -1e30f, v1 = -1e30f;
            int i0 = 0, i1 = 0;
            for (int e2 = 0; e2 < NEXP; e2++) {
                const float v = Lr[e2];
                if (v > v0)      { v1 = v0; i1 = i0; v0 = v; i0 = e2; }
                else if (v > v1) { v1 = v; i1 = e2; }
            }
            const float t  = __expf(v1 - v0);
            const float w0 = 1.0f / (1.0f + t);
            const size_t g = rowBase + rrow;
            out[2 * g]     = w0;
            out[2 * g + 1] = 1.0f - w0;
            float* oi = out + 2 * (size_t)BTOK;
            oi[2 * g]     = (float)i0;
            oi[2 * g + 1] = (float)i1;
        }
        __syncthreads();
    }
}

extern "C" void kernel_launch(void* const* d_in, const int* in_sizes, int n_in,
                              void* d_out, int out_size)
{
    const float* h    = (const float*)d_in[0];
    const float* w    = (const float*)d_in[1];
    const float* bias = (const float*)d_in[2];
    float* out        = (float*)d_out;

    wsplit_kernel<<<(NEXP * DIMK) / 256, 256>>>(w);

    cudaFuncSetAttribute(mome_gate_hyb,
                         cudaFuncAttributeMaxDynamicSharedMemorySize, SMEM_BYTES);
    mome_gate_hyb<<<BTOK / MTILE, NTHR, SMEM_BYTES>>>(h, w, bias, out);
}